// round 1
// baseline (speedup 1.0000x reference)
#include <cuda_runtime.h>
#include <cuda_bf16.h>
#include <cstdint>
#include <cstddef>

// Problem constants (fixed shapes from reference setup_inputs)
#define BB   2
#define HH   8
#define LL   4096
#define DKK  128
#define DVV  128
#define CC   32
#define NCH  (LL / CC)       // 128 chunks per head
#define BHT  (BB * HH)       // 16 batch-heads
#define SDK  132             // padded smem row stride for 128-float rows (bank spread)
#define SKT  36              // padded kT row stride
#define SAT  33              // padded attn row stride

#define OUT_ELEMS  ((size_t)BB * HH * LL * DVV)          // 8388608
#define S_ELEMS    ((size_t)BB * HH * DKK * DVV)         // 262144

// ---------------- scratch (device globals; no allocation allowed) ----------------
__device__ float g_qT[(size_t)BHT * NCH * DKK * CC];   // [bh][ch][d][i]
__device__ float g_kT[(size_t)BHT * NCH * DKK * CC];   // [bh][ch][d][i]
__device__ float g_wT[(size_t)BHT * NCH * DKK * CC];   // [bh][ch][d][i]
__device__ float g_u [(size_t)BHT * NCH * CC * DVV];   // [bh][ch][i][d]
__device__ float g_at[(size_t)BHT * NCH * CC * CC];    // [bh][ch][i][j] masked lower-incl-diag

__device__ __forceinline__ float dot4(float4 a, float4 b) {
    return a.x * b.x + a.y * b.y + a.z * b.z + a.w * b.w;
}
__device__ __forceinline__ void fma4(float4& acc, float a, float4 b) {
    acc.x += a * b.x; acc.y += a * b.y; acc.z += a * b.z; acc.w += a * b.w;
}

// =====================================================================
// Phase 1: per-chunk (fully parallel) — l2norm, tri-inverse, u, w, attn
// grid (NCH, BHT), 256 threads
// =====================================================================
__global__ __launch_bounds__(256) void phase1_kernel(
    const float* __restrict__ gq, const float* __restrict__ gk,
    const float* __restrict__ gv, const float* __restrict__ gbeta)
{
    extern __shared__ float sm[];
    float* sq    = sm;                       // CC*SDK
    float* sk    = sq + CC * SDK;            // CC*SDK
    float* sv    = sk + CC * SDK;            // CC*SDK
    float* sA    = sv + CC * SDK;            // CC*(CC+1)
    float* sbeta = sA + CC * (CC + 1);       // CC
    float* sqs   = sbeta + CC;               // CC
    float* sks   = sqs + CC;                 // CC

    const int t  = threadIdx.x;
    const int ch = blockIdx.x;
    const int bh = blockIdx.y;
    const size_t gbase = ((size_t)bh * LL + (size_t)ch * CC) * DKK;

    // ---- load q,k,v chunk (32x128 each) ----
    {
        const float4* q4 = (const float4*)(gq + gbase);
        const float4* k4 = (const float4*)(gk + gbase);
        const float4* v4 = (const float4*)(gv + gbase);
        for (int idx = t; idx < CC * DKK / 4; idx += 256) {
            int r = idx >> 5, c4 = idx & 31;
            ((float4*)(sq + r * SDK))[c4] = q4[idx];
            ((float4*)(sk + r * SDK))[c4] = k4[idx];
            ((float4*)(sv + r * SDK))[c4] = v4[idx];
        }
    }
    if (t < CC) sbeta[t] = gbeta[(size_t)bh * LL + (size_t)ch * CC + t];
    __syncthreads();

    // ---- row l2 norms ----
    {
        int row = t >> 3, seg = t & 7;
        const float4* qr = (const float4*)(sq + row * SDK) + seg * 4;
        const float4* kr = (const float4*)(sk + row * SDK) + seg * 4;
        float s2q = 0.f, s2k = 0.f;
        #pragma unroll
        for (int i2 = 0; i2 < 4; i2++) {
            float4 a = qr[i2]; s2q += a.x * a.x + a.y * a.y + a.z * a.z + a.w * a.w;
            float4 b = kr[i2]; s2k += b.x * b.x + b.y * b.y + b.z * b.z + b.w * b.w;
        }
        #pragma unroll
        for (int off = 4; off; off >>= 1) {
            s2q += __shfl_down_sync(0xffffffffu, s2q, off, 8);
            s2k += __shfl_down_sync(0xffffffffu, s2k, off, 8);
        }
        if (seg == 0) { sqs[row] = rsqrtf(s2q + 1e-6f); sks[row] = rsqrtf(s2k + 1e-6f); }
    }
    __syncthreads();
    {
        int row = t >> 3, seg = t & 7;
        float a = sqs[row], b = sks[row];
        float4* qr = (float4*)(sq + row * SDK) + seg * 4;
        float4* kr = (float4*)(sk + row * SDK) + seg * 4;
        #pragma unroll
        for (int i2 = 0; i2 < 4; i2++) {
            float4 x = qr[i2]; x.x *= a; x.y *= a; x.z *= a; x.w *= a; qr[i2] = x;
            float4 y = kr[i2]; y.x *= b; y.y *= b; y.z *= b; y.w *= b; kr[i2] = y;
        }
    }
    __syncthreads();

    const size_t tbase = ((size_t)(bh * NCH + ch)) * DKK * CC;
    const size_t abase = ((size_t)(bh * NCH + ch)) * CC * CC;

    // ---- store q̂ᵀ, k̂ᵀ transposed ----
    {
        int d = t >> 1, i0 = (t & 1) * 16;
        #pragma unroll
        for (int ii = 0; ii < 16; ii += 4) {
            float4 a = make_float4(sq[(i0 + ii) * SDK + d], sq[(i0 + ii + 1) * SDK + d],
                                   sq[(i0 + ii + 2) * SDK + d], sq[(i0 + ii + 3) * SDK + d]);
            *(float4*)(g_qT + tbase + (size_t)d * CC + i0 + ii) = a;
            float4 b = make_float4(sk[(i0 + ii) * SDK + d], sk[(i0 + ii + 1) * SDK + d],
                                   sk[(i0 + ii + 2) * SDK + d], sk[(i0 + ii + 3) * SDK + d]);
            *(float4*)(g_kT + tbase + (size_t)d * CC + i0 + ii) = b;
        }
    }

    // ---- A = -(β_i k̂_i·k̂_j) strictly lower ; attn = (q̂_i·k̂_j) lower incl diag ----
    {
        int ti = t >> 4, tj = t & 15;
        int i0 = 2 * ti, j0 = 2 * tj;
        float dkk00 = 0, dkk01 = 0, dkk10 = 0, dkk11 = 0;
        float dqk00 = 0, dqk01 = 0, dqk10 = 0, dqk11 = 0;
        const float4* ki0 = (const float4*)(sk + i0 * SDK);
        const float4* ki1 = (const float4*)(sk + (i0 + 1) * SDK);
        const float4* kj0 = (const float4*)(sk + j0 * SDK);
        const float4* kj1 = (const float4*)(sk + (j0 + 1) * SDK);
        const float4* qi0 = (const float4*)(sq + i0 * SDK);
        const float4* qi1 = (const float4*)(sq + (i0 + 1) * SDK);
        #pragma unroll 8
        for (int d4 = 0; d4 < 32; d4++) {
            float4 a0 = ki0[d4], a1 = ki1[d4];
            float4 b0 = kj0[d4], b1 = kj1[d4];
            float4 c0 = qi0[d4], c1 = qi1[d4];
            dkk00 += dot4(a0, b0); dkk01 += dot4(a0, b1);
            dkk10 += dot4(a1, b0); dkk11 += dot4(a1, b1);
            dqk00 += dot4(c0, b0); dqk01 += dot4(c0, b1);
            dqk10 += dot4(c1, b0); dqk11 += dot4(c1, b1);
        }
        float bi0 = sbeta[i0], bi1 = sbeta[i0 + 1];
        sA[i0 * (CC + 1) + j0]           = (i0 > j0)         ? -bi0 * dkk00 : 0.f;
        sA[i0 * (CC + 1) + j0 + 1]       = (i0 > j0 + 1)     ? -bi0 * dkk01 : 0.f;
        sA[(i0 + 1) * (CC + 1) + j0]     = (i0 + 1 > j0)     ? -bi1 * dkk10 : 0.f;
        sA[(i0 + 1) * (CC + 1) + j0 + 1] = (i0 + 1 > j0 + 1) ? -bi1 * dkk11 : 0.f;
        g_at[abase + i0 * CC + j0]             = (i0 >= j0)         ? dqk00 : 0.f;
        g_at[abase + i0 * CC + j0 + 1]         = (i0 >= j0 + 1)     ? dqk01 : 0.f;
        g_at[abase + (i0 + 1) * CC + j0]       = (i0 + 1 >= j0)     ? dqk10 : 0.f;
        g_at[abase + (i0 + 1) * CC + j0 + 1]   = (i0 + 1 >= j0 + 1) ? dqk11 : 0.f;
    }
    __syncthreads();

    // ---- forward substitution (exact reference recurrence), warp 0 ----
    if (t < 32) {
        int lane = t;
        for (int i = 1; i < CC; i++) {
            float s = 0.f;
            if (lane < i) {
                for (int kk = lane + 1; kk < i; kk++)
                    s += sA[i * (CC + 1) + kk] * sA[kk * (CC + 1) + lane];
            }
            __syncwarp();
            if (lane < i) sA[i * (CC + 1) + lane] += s;
            __syncwarp();
        }
        sA[lane * (CC + 1) + lane] = 1.0f;   // inv += I
    }
    __syncthreads();

    // ---- fold β into inv: Abeta[i][j] = inv[i][j] * β[j] ----
    for (int idx = t; idx < CC * CC; idx += 256) {
        int i = idx >> 5, j = idx & 31;
        sA[i * (CC + 1) + j] *= sbeta[j];
    }
    __syncthreads();

    // ---- u = Abeta @ v ; w = Abeta @ k̂ (w stored transposed) ----
    {
        const size_t ubase = ((size_t)(bh * NCH + ch)) * CC * DVV;
        int p = t >> 4, dseg = t & 15;
        int i0 = 2 * p, d0 = 8 * dseg;
        float4 u0a = {0,0,0,0}, u0b = {0,0,0,0}, u1a = {0,0,0,0}, u1b = {0,0,0,0};
        float4 w0a = {0,0,0,0}, w0b = {0,0,0,0}, w1a = {0,0,0,0}, w1b = {0,0,0,0};
        #pragma unroll 4
        for (int j = 0; j < CC; j++) {
            float a0 = sA[i0 * (CC + 1) + j];
            float a1 = sA[(i0 + 1) * (CC + 1) + j];
            float4 va = *(const float4*)(sv + j * SDK + d0);
            float4 vb = *(const float4*)(sv + j * SDK + d0 + 4);
            float4 ka = *(const float4*)(sk + j * SDK + d0);
            float4 kb = *(const float4*)(sk + j * SDK + d0 + 4);
            fma4(u0a, a0, va); fma4(u0b, a0, vb);
            fma4(u1a, a1, va); fma4(u1b, a1, vb);
            fma4(w0a, a0, ka); fma4(w0b, a0, kb);
            fma4(w1a, a1, ka); fma4(w1b, a1, kb);
        }
        *(float4*)(g_u + ubase + (size_t)i0 * DVV + d0)           = u0a;
        *(float4*)(g_u + ubase + (size_t)i0 * DVV + d0 + 4)       = u0b;
        *(float4*)(g_u + ubase + (size_t)(i0 + 1) * DVV + d0)     = u1a;
        *(float4*)(g_u + ubase + (size_t)(i0 + 1) * DVV + d0 + 4) = u1b;
        float w0arr[8] = {w0a.x, w0a.y, w0a.z, w0a.w, w0b.x, w0b.y, w0b.z, w0b.w};
        float w1arr[8] = {w1a.x, w1a.y, w1a.z, w1a.w, w1b.x, w1b.y, w1b.z, w1b.w};
        #pragma unroll
        for (int dd = 0; dd < 8; dd++) {
            g_wT[tbase + (size_t)(d0 + dd) * CC + i0]     = w0arr[dd];
            g_wT[tbase + (size_t)(d0 + dd) * CC + i0 + 1] = w1arr[dd];
        }
    }
}

// =====================================================================
// Phase 2: sequential chunk scan; dv split into 8 slices of 16 columns.
// grid (8, BHT), 256 threads.  S-slice (128x16) lives in smem.
// =====================================================================
__global__ __launch_bounds__(256) void phase2_kernel(
    float* __restrict__ out, float* __restrict__ Sout)
{
    extern __shared__ float sm[];
    float* sWQ = sm;                     // [128][64]: cols 0..31 = wT, 32..63 = qT
    float* skT = sWQ + 128 * 64;         // [128][SKT]
    float* sS  = skT + 128 * SKT;        // [128][16]
    float* sU  = sS + 128 * 16;          // [32][16]   (u, then u')
    float* sAt = sU + 32 * 16;           // [32][SAT]

    const int t     = threadIdx.x;
    const int slice = blockIdx.x;
    const int bh    = blockIdx.y;
    const int c0    = slice * 16;

    for (int idx = t; idx < 128 * 16; idx += 256) sS[idx] = 0.f;

    const int i  = t >> 2;        // 0..63 output row of P
    const int cq = t & 3;         // col quad
    const int r0 = i * 2;         // S rows owned in update

    for (int ch = 0; ch < NCH; ch++) {
        __syncthreads();   // prior-iter readers done before overwriting staging
        const size_t tb = ((size_t)(bh * NCH + ch)) * DKK * CC;
        const size_t ub = ((size_t)(bh * NCH + ch)) * CC * DVV;
        const size_t ab = ((size_t)(bh * NCH + ch)) * CC * CC;

        // stage wT|qT, kT
        {
            const float4* w4 = (const float4*)(g_wT + tb);
            const float4* q4 = (const float4*)(g_qT + tb);
            const float4* k4 = (const float4*)(g_kT + tb);
            for (int idx = t; idx < 1024; idx += 256) {
                int r = idx >> 3, ii = (idx & 7) << 2;
                *(float4*)(sWQ + r * 64 + ii)      = w4[idx];
                *(float4*)(sWQ + r * 64 + 32 + ii) = q4[idx];
                *(float4*)(skT + r * SKT + ii)     = k4[idx];
            }
        }
        // stage u-slice (threads 0..127) and attn (all threads)
        if (t < 128) {
            int ir = t >> 2, c4 = (t & 3) << 2;
            *(float4*)(sU + ir * 16 + c4) =
                *(const float4*)(g_u + ub + (size_t)ir * DVV + c0 + c4);
        }
        {
            int ir = t >> 3, jj = (t & 7) << 2;
            float4 a = *(const float4*)(g_at + ab + (size_t)ir * CC + jj);
            sAt[ir * SAT + jj]     = a.x;
            sAt[ir * SAT + jj + 1] = a.y;
            sAt[ir * SAT + jj + 2] = a.z;
            sAt[ir * SAT + jj + 3] = a.w;
        }
        __syncthreads();

        // P = [w ; q̂] @ S   (64x16); rows<32 -> w@S, rows>=32 -> q@S
        float4 acc = make_float4(0.f, 0.f, 0.f, 0.f);
        {
            const float* wq = sWQ + i;
            const float4* Sc = (const float4*)sS + cq;
            #pragma unroll 8
            for (int r = 0; r < 128; r++) {
                float a = wq[r * 64];
                float4 s4 = Sc[r * 4];
                fma4(acc, a, s4);
            }
        }
        if (i < 32) {  // u' = u - wS
            float4 u4 = *(const float4*)(sU + i * 16 + cq * 4);
            u4.x -= acc.x; u4.y -= acc.y; u4.z -= acc.z; u4.w -= acc.w;
            *(float4*)(sU + i * 16 + cq * 4) = u4;
        }
        __syncthreads();

        if (i >= 32) {  // o = q̂S + attn @ u'
            int ii2 = i - 32;
            const float* at = sAt + ii2 * SAT;
            #pragma unroll 8
            for (int j = 0; j < CC; j++) {
                float a = at[j];
                float4 u4 = *(const float4*)(sU + j * 16 + cq * 4);
                fma4(acc, a, u4);
            }
            size_t off = ((size_t)bh * LL + (size_t)ch * CC + ii2) * DVV + c0 + cq * 4;
            *(float4*)(out + off) = acc;
        }

        // S += k̂ᵀ @ u'  (each thread owns rows r0,r0+1 x 4 cols — exclusive)
        {
            float4 s0 = *(const float4*)(sS + r0 * 16 + cq * 4);
            float4 s1 = *(const float4*)(sS + (r0 + 1) * 16 + cq * 4);
            const float* k0p = skT + r0 * SKT;
            const float* k1p = skT + (r0 + 1) * SKT;
            #pragma unroll 8
            for (int j = 0; j < CC; j++) {
                float k0 = k0p[j], k1 = k1p[j];
                float4 u4 = *(const float4*)(sU + j * 16 + cq * 4);
                fma4(s0, k0, u4);
                fma4(s1, k1, u4);
            }
            *(float4*)(sS + r0 * 16 + cq * 4)       = s0;
            *(float4*)(sS + (r0 + 1) * 16 + cq * 4) = s1;
        }
    }

    if (Sout != nullptr) {
        __syncthreads();
        size_t sb = (size_t)bh * DKK * DVV;
        *(float4*)(Sout + sb + (size_t)r0 * DVV + c0 + cq * 4) =
            *(const float4*)(sS + r0 * 16 + cq * 4);
        *(float4*)(Sout + sb + (size_t)(r0 + 1) * DVV + c0 + cq * 4) =
            *(const float4*)(sS + (r0 + 1) * 16 + cq * 4);
    }
}

// =====================================================================
// Launch
// =====================================================================
#define P1_SMEM ((3 * CC * SDK + CC * (CC + 1) + 3 * CC) * (int)sizeof(float))       // 55296
#define P2_SMEM ((128 * 64 + 128 * SKT + 128 * 16 + 32 * 16 + 32 * SAT) * (int)sizeof(float)) // 65664

extern "C" void kernel_launch(void* const* d_in, const int* in_sizes, int n_in,
                              void* d_out, int out_size)
{
    const float* q    = (const float*)d_in[0];
    const float* k    = (const float*)d_in[1];
    const float* v    = (const float*)d_in[2];
    const float* beta = (const float*)d_in[3];
    float* out = (float*)d_out;
    // Reference returns (out, S). If harness flattened both, write S after out.
    float* Sout = ((size_t)out_size >= OUT_ELEMS + S_ELEMS) ? (out + OUT_ELEMS) : nullptr;

    cudaFuncSetAttribute(phase1_kernel, cudaFuncAttributeMaxDynamicSharedMemorySize, P1_SMEM);
    cudaFuncSetAttribute(phase2_kernel, cudaFuncAttributeMaxDynamicSharedMemorySize, P2_SMEM);

    phase1_kernel<<<dim3(NCH, BHT), 256, P1_SMEM>>>(q, k, v, beta);
    phase2_kernel<<<dim3(8, BHT), 256, P2_SMEM>>>(out, Sout);
}